// round 5
// baseline (speedup 1.0000x reference)
#include <cuda_runtime.h>
#include <math.h>

#define NN 100000
#define EE 1200000
#define FF 64
#define DD 32
#define GG 64

// ---------------- scratch ----------------
__device__ float g_Af[NN * FF];
__device__ float g_Bf[NN * FF];
__device__ float g_As[NN * FF];
__device__ float g_Bs[NN * FF];
__device__ float g_h [NN * FF];   // conv accumulator (init = x, residual folded in)
__device__ float g_x2[NN * FF];
__device__ float g_gsum [GG * FF];
__device__ float g_gss  [GG * FF];
__device__ float g_alpha[GG * FF];
__device__ float g_beta [GG * FF];
__device__ float g_cnt[GG];
__device__ int   g_use64;

// ---------------- int32/int64 runtime detection ----------------
__global__ void k_detect(const int2* __restrict__ idx) {
    __shared__ int any;
    if (threadIdx.x == 0) any = 0;
    __syncthreads();
    int2 v = idx[threadIdx.x];
    if (v.y != 0) any = 1;
    __syncthreads();
    if (threadIdx.x == 0) g_use64 = (any == 0) ? 1 : 0;
}

// ---------------- node linear: Af,Bf,As,Bs + h = x ----------------
// 8 lanes per node, 2 nodes per thread; 2 blocks/SM for latency hiding.
__global__ __launch_bounds__(256, 2) void k_node(
    const float* __restrict__ x,
    const float* __restrict__ Wf, const float* __restrict__ bf,
    const float* __restrict__ Ws, const float* __restrict__ bs)
{
    __shared__ float sW[128 * 64];            // full W (32 KB)
    const int tid  = threadIdx.x;
    const int lane = tid & 31;
    const int l    = lane & 7;
    const int sub  = lane >> 3;
    const int warp = tid >> 5;
    const int nb   = (blockIdx.x * 8 + warp) * 8 + sub;   // nodes nb, nb+4

    float xa[2][8];
    bool act[2];
    #pragma unroll
    for (int j = 0; j < 2; j++) {
        const int n = nb + 4 * j;
        act[j] = (n < NN);
        if (act[j]) {
            const float4* xp = (const float4*)(x + (size_t)n * FF);
            float4 v0 = xp[l], v1 = xp[l + 8];
            xa[j][0]=v0.x; xa[j][1]=v0.y; xa[j][2]=v0.z; xa[j][3]=v0.w;
            xa[j][4]=v1.x; xa[j][5]=v1.y; xa[j][6]=v1.z; xa[j][7]=v1.w;
            float4* hp = (float4*)(g_h + (size_t)n * FF);
            hp[l] = v0; hp[l + 8] = v1;
        } else {
            #pragma unroll
            for (int t = 0; t < 8; t++) xa[j][t] = 0.f;
        }
    }

    const float4* sW4 = (const float4*)sW;

    #pragma unroll 1
    for (int m = 0; m < 2; m++) {
        const float* Wsrc = (m == 0) ? Wf : Ws;
        const float* bias = (m == 0) ? bf : bs;
        __syncthreads();
        for (int i = tid; i < 8192; i += 256) sW[i] = Wsrc[i];
        __syncthreads();

        float accA[2][8], accB[2][8];
        #pragma unroll
        for (int j = 0; j < 2; j++) {
            #pragma unroll
            for (int t = 0; t < 4; t++) {
                accA[j][t]   = bias[4*l + t];
                accA[j][4+t] = bias[32 + 4*l + t];
                accB[j][t]   = 0.f;
                accB[j][4+t] = 0.f;
            }
        }

        #pragma unroll
        for (int k = 0; k < 64; k++) {
            const int src = (lane & 24) | ((k >> 2) & 7);
            float4 wa0 = sW4[k * 16 + l];
            float4 wa1 = sW4[k * 16 + 8 + l];
            float4 wb0 = sW4[(64 + k) * 16 + l];
            float4 wb1 = sW4[(64 + k) * 16 + 8 + l];
            #pragma unroll
            for (int j = 0; j < 2; j++) {
                float xv = __shfl_sync(0xffffffffu, (k < 32) ? xa[j][k & 3] : xa[j][4 + (k & 3)], src);
                accA[j][0] += xv * wa0.x; accA[j][1] += xv * wa0.y; accA[j][2] += xv * wa0.z; accA[j][3] += xv * wa0.w;
                accA[j][4] += xv * wa1.x; accA[j][5] += xv * wa1.y; accA[j][6] += xv * wa1.z; accA[j][7] += xv * wa1.w;
                accB[j][0] += xv * wb0.x; accB[j][1] += xv * wb0.y; accB[j][2] += xv * wb0.z; accB[j][3] += xv * wb0.w;
                accB[j][4] += xv * wb1.x; accB[j][5] += xv * wb1.y; accB[j][6] += xv * wb1.z; accB[j][7] += xv * wb1.w;
            }
        }

        #pragma unroll
        for (int j = 0; j < 2; j++) {
            if (!act[j]) continue;
            const int n = nb + 4 * j;
            float4* dA = (float4*)((m == 0 ? g_Af : g_As) + (size_t)n * FF);
            float4* dB = (float4*)((m == 0 ? g_Bf : g_Bs) + (size_t)n * FF);
            dA[l]     = make_float4(accA[j][0], accA[j][1], accA[j][2], accA[j][3]);
            dA[l + 8] = make_float4(accA[j][4], accA[j][5], accA[j][6], accA[j][7]);
            dB[l]     = make_float4(accB[j][0], accB[j][1], accB[j][2], accB[j][3]);
            dB[l + 8] = make_float4(accB[j][4], accB[j][5], accB[j][6], accB[j][7]);
        }
    }
}

// ---------------- edge kernel ----------------
__device__ __forceinline__ float msgval(float f, float s) {
    float sig = __fdividef(1.f, 1.f + __expf(-f));
    float sp  = fmaxf(s, 0.f) + __logf(1.f + __expf(-fabsf(s)));
    return sig * sp;
}

// 8 lanes per edge, 2 edges per thread; 2 blocks/SM (<=128 regs).
// Warp = 8 edges, block = 8 warps = 64 edges. EE % 64 == 0.
__global__ __launch_bounds__(256, 2) void k_edge(
    const int* __restrict__ i32, const long long* __restrict__ i64,
    const float* __restrict__ attr,
    const float* __restrict__ Wf, const float* __restrict__ Ws)
{
    __shared__ float sF[2048], sS[2048];
    const int tid = threadIdx.x;
    for (int i = tid; i < 2048; i += 256) { sF[i] = Wf[8192 + i]; sS[i] = Ws[8192 + i]; }
    __syncthreads();

    const int lane = tid & 31;
    const int l    = lane & 7;
    const int sub  = lane >> 3;
    const int warp = tid >> 5;
    const int use64 = g_use64;
    const float4* sF4 = (const float4*)sF;
    const float4* sS4 = (const float4*)sS;

    const int ebase = blockIdx.x * 64 + warp * 8 + sub;  // edges ebase, ebase+4

    int dIdx[2];
    float av[2][4];
    float accf[2][8], accs[2][8];

    #pragma unroll
    for (int j = 0; j < 2; j++) {
        const int e = ebase + 4 * j;
        long long s, d;
        if (use64) { s = i64[e]; d = i64[EE + e]; }
        else       { s = i32[e]; d = i32[EE + e]; }
        dIdx[j] = (int)d;

        float4 a = ((const float4*)attr)[(size_t)e * 8 + l];
        av[j][0] = a.x; av[j][1] = a.y; av[j][2] = a.z; av[j][3] = a.w;

        const float4* pAf = (const float4*)(g_Af + (size_t)d * FF);
        const float4* pBf = (const float4*)(g_Bf + (size_t)s * FF);
        const float4* pAs = (const float4*)(g_As + (size_t)d * FF);
        const float4* pBs = (const float4*)(g_Bs + (size_t)s * FF);
        float4 f0 = pAf[l], f1 = pAf[l + 8];
        float4 g0 = pBf[l], g1 = pBf[l + 8];
        float4 s0 = pAs[l], s1 = pAs[l + 8];
        float4 t0 = pBs[l], t1 = pBs[l + 8];
        accf[j][0]=f0.x+g0.x; accf[j][1]=f0.y+g0.y; accf[j][2]=f0.z+g0.z; accf[j][3]=f0.w+g0.w;
        accf[j][4]=f1.x+g1.x; accf[j][5]=f1.y+g1.y; accf[j][6]=f1.z+g1.z; accf[j][7]=f1.w+g1.w;
        accs[j][0]=s0.x+t0.x; accs[j][1]=s0.y+t0.y; accs[j][2]=s0.z+t0.z; accs[j][3]=s0.w+t0.w;
        accs[j][4]=s1.x+t1.x; accs[j][5]=s1.y+t1.y; accs[j][6]=s1.z+t1.z; accs[j][7]=s1.w+t1.w;
    }

    #pragma unroll
    for (int k = 0; k < 32; k++) {
        const int src = (lane & 24) | (k >> 2);
        float4 wf0 = sF4[k * 16 + l];
        float4 wf1 = sF4[k * 16 + 8 + l];
        float4 ws0 = sS4[k * 16 + l];
        float4 ws1 = sS4[k * 16 + 8 + l];
        #pragma unroll
        for (int j = 0; j < 2; j++) {
            float ak = __shfl_sync(0xffffffffu, av[j][k & 3], src);
            accf[j][0] += ak * wf0.x; accf[j][1] += ak * wf0.y; accf[j][2] += ak * wf0.z; accf[j][3] += ak * wf0.w;
            accf[j][4] += ak * wf1.x; accf[j][5] += ak * wf1.y; accf[j][6] += ak * wf1.z; accf[j][7] += ak * wf1.w;
            accs[j][0] += ak * ws0.x; accs[j][1] += ak * ws0.y; accs[j][2] += ak * ws0.z; accs[j][3] += ak * ws0.w;
            accs[j][4] += ak * ws1.x; accs[j][5] += ak * ws1.y; accs[j][6] += ak * ws1.z; accs[j][7] += ak * ws1.w;
        }
    }

    #pragma unroll
    for (int j = 0; j < 2; j++) {
        float4 m0 = make_float4(msgval(accf[j][0], accs[j][0]), msgval(accf[j][1], accs[j][1]),
                                msgval(accf[j][2], accs[j][2]), msgval(accf[j][3], accs[j][3]));
        float4 m1 = make_float4(msgval(accf[j][4], accs[j][4]), msgval(accf[j][5], accs[j][5]),
                                msgval(accf[j][6], accs[j][6]), msgval(accf[j][7], accs[j][7]));
        float4* ph = (float4*)(g_h + (size_t)dIdx[j] * FF);
        atomicAdd(ph + l,     m0);
        atomicAdd(ph + l + 8, m1);
    }
}

// ---------------- graph-norm ----------------
__global__ void k_zero() {
    int i = blockIdx.x * 256 + threadIdx.x;
    if (i < GG * FF) { g_gsum[i] = 0.f; g_gss[i] = 0.f; }
}

__device__ __forceinline__ long long bget(const int* b32, const long long* b64, int u, int i) {
    return u ? b64[i] : (long long)b32[i];
}

__global__ __launch_bounds__(256) void k_stats(const int* __restrict__ b32,
                                               const long long* __restrict__ b64) {
    const int g = blockIdx.x >> 3;
    const int sp = blockIdx.x & 7;
    const int u = g_use64;

    int lo = 0, hi = NN;
    while (lo < hi) { int mid = (lo + hi) >> 1; if (bget(b32, b64, u, mid) < (long long)g) lo = mid + 1; else hi = mid; }
    const int s0 = lo;
    hi = NN;
    while (lo < hi) { int mid = (lo + hi) >> 1; if (bget(b32, b64, u, mid) < (long long)(g + 1)) lo = mid + 1; else hi = mid; }
    const int s1 = lo;

    const int len = s1 - s0;
    const int chunk = (len + 7) >> 3;
    const int a = s0 + sp * chunk;
    const int b = min(a + chunk, s1);

    const int f = threadIdx.x & 63;
    const int j = threadIdx.x >> 6;
    float sum = 0.f, ss = 0.f;
    for (int n = a + j; n < b; n += 4) {
        float v = g_h[(size_t)n * FF + f];
        sum += v; ss += v * v;
    }
    __shared__ float r1[256], r2[256];
    r1[threadIdx.x] = sum; r2[threadIdx.x] = ss;
    __syncthreads();
    if (j == 0) {
        float t1 = r1[f] + r1[64 + f] + r1[128 + f] + r1[192 + f];
        float t2 = r2[f] + r2[64 + f] + r2[128 + f] + r2[192 + f];
        atomicAdd(&g_gsum[g * 64 + f], t1);
        atomicAdd(&g_gss [g * 64 + f], t2);
    }
    if (sp == 0 && threadIdx.x == 0) g_cnt[g] = (float)len;
}

__global__ void k_prep(const float* __restrict__ gw, const float* __restrict__ gb,
                       const float* __restrict__ gm) {
    int i = blockIdx.x * 256 + threadIdx.x;
    if (i >= GG * FF) return;
    int f = i & 63, g = i >> 6;
    float c    = fmaxf(g_cnt[g], 1.f);
    float inv  = __fdividef(1.f, c);
    float mean = g_gsum[i] * inv;
    float ex2  = g_gss[i] * inv;
    float sub  = gm[f] * mean;
    float var  = ex2 - 2.f * sub * mean + sub * sub;
    float rstd = rsqrtf(var + 1e-5f);
    float al   = gw[f] * rstd;
    g_alpha[i] = al;
    g_beta[i]  = gb[f] - al * sub;
}

__global__ void k_apply(float* __restrict__ out, const int* __restrict__ b32,
                        const long long* __restrict__ b64, int to_internal) {
    int i = blockIdx.x * 256 + threadIdx.x;
    if (i >= NN * FF) return;
    int n = i >> 6, f = i & 63;
    int g = g_use64 ? (int)b64[n] : b32[n];
    float y = g_alpha[g * 64 + f] * g_h[i] + g_beta[g * 64 + f];
    y = (y >= 0.f) ? y : 0.01f * y;
    if (to_internal) g_x2[i] = y; else out[i] = y;
}

// ---------------- launch ----------------
extern "C" void kernel_launch(void* const* d_in, const int* in_sizes, int n_in,
                              void* d_out, int out_size) {
    const float* x    = (const float*)d_in[0];
    const void*  idx  = d_in[1];
    const float* attr = (const float*)d_in[2];
    const void*  bat  = d_in[3];
    const float* Wf1 = (const float*)d_in[4];  const float* bf1 = (const float*)d_in[5];
    const float* Ws1 = (const float*)d_in[6];  const float* bs1 = (const float*)d_in[7];
    const float* gw1 = (const float*)d_in[8];  const float* gb1 = (const float*)d_in[9];
    const float* gm1 = (const float*)d_in[10];
    const float* Wf2 = (const float*)d_in[11]; const float* bf2 = (const float*)d_in[12];
    const float* Ws2 = (const float*)d_in[13]; const float* bs2 = (const float*)d_in[14];
    const float* gw2 = (const float*)d_in[15]; const float* gb2 = (const float*)d_in[16];
    const float* gm2 = (const float*)d_in[17];
    float* out = (float*)d_out;

    const int*       i32 = (const int*)idx;
    const long long* i64 = (const long long*)idx;
    const int*       b32 = (const int*)bat;
    const long long* b64 = (const long long*)bat;

    float* x2ptr = nullptr;
    cudaGetSymbolAddress((void**)&x2ptr, g_x2);

    const int NB_NODE = (NN + 63) / 64;      // 64 nodes / block
    const int NB_EDGE = EE / 64;             // 18750
    const int NB_ELEM = (NN * FF) / 256;

    k_detect<<<1, 256>>>((const int2*)idx);

    // layer 1  (zero before edge so ncu -s 5 lands on k_edge)
    k_node <<<NB_NODE, 256>>>(x, Wf1, bf1, Ws1, bs1);
    k_zero <<<16, 256>>>();
    k_edge <<<NB_EDGE, 256>>>(i32, i64, attr, Wf1, Ws1);
    k_stats<<<GG * 8, 256>>>(b32, b64);
    k_prep <<<16, 256>>>(gw1, gb1, gm1);
    k_apply<<<NB_ELEM, 256>>>(out, b32, b64, 1);

    // layer 2
    k_node <<<NB_NODE, 256>>>(x2ptr, Wf2, bf2, Ws2, bs2);
    k_zero <<<16, 256>>>();
    k_edge <<<NB_EDGE, 256>>>(i32, i64, attr, Wf2, Ws2);
    k_stats<<<GG * 8, 256>>>(b32, b64);
    k_prep <<<16, 256>>>(gw2, gb2, gm2);
    k_apply<<<NB_ELEM, 256>>>(out, b32, b64, 0);
}

// round 6
// speedup vs baseline: 1.0464x; 1.0464x over previous
#include <cuda_runtime.h>
#include <math.h>

#define NN 100000
#define EE 1200000
#define FF 64
#define DD 32
#define GG 64

typedef unsigned long long u64;

// packed f32x2 helpers (sm_100+; ptxas never auto-generates these)
#define FMA2(d, a, b, c) asm("fma.rn.f32x2 %0, %1, %2, %3;" : "=l"(d) : "l"(a), "l"(b), "l"(c))
#define ADD2(d, a, b)    asm("add.rn.f32x2 %0, %1, %2;"     : "=l"(d) : "l"(a), "l"(b))
#define PACK2(d, s)      asm("mov.b64 %0, {%1, %1};"        : "=l"(d) : "r"(__float_as_uint(s)))
#define UNPACK2(lo, hi, s) asm("mov.b64 {%0, %1}, %2;" : "=r"(lo), "=r"(hi) : "l"(s))

// ---------------- scratch ----------------
__device__ float g_Af[NN * FF];
__device__ float g_Bf[NN * FF];
__device__ float g_As[NN * FF];
__device__ float g_Bs[NN * FF];
__device__ float g_h [NN * FF];   // conv accumulator (init = x, residual folded in)
__device__ float g_x2[NN * FF];
__device__ float g_gsum [GG * FF];
__device__ float g_gss  [GG * FF];
__device__ float g_alpha[GG * FF];
__device__ float g_beta [GG * FF];
__device__ float g_cnt[GG];
__device__ int   g_use64;

// ---------------- int32/int64 runtime detection ----------------
__global__ void k_detect(const int2* __restrict__ idx) {
    __shared__ int any;
    if (threadIdx.x == 0) any = 0;
    __syncthreads();
    int2 v = idx[threadIdx.x];
    if (v.y != 0) any = 1;
    __syncthreads();
    if (threadIdx.x == 0) g_use64 = (any == 0) ? 1 : 0;
}

// ---------------- node linear: Af,Bf,As,Bs + h = x ----------------
// 8 lanes per node, 2 nodes per thread; packed f32x2 FMAs.
__global__ __launch_bounds__(256, 2) void k_node(
    const float* __restrict__ x,
    const float* __restrict__ Wf, const float* __restrict__ bf,
    const float* __restrict__ Ws, const float* __restrict__ bs)
{
    __shared__ float sW[128 * 64];            // full W (32 KB)
    const int tid  = threadIdx.x;
    const int lane = tid & 31;
    const int l    = lane & 7;
    const int sub  = lane >> 3;
    const int warp = tid >> 5;
    const int nb   = (blockIdx.x * 8 + warp) * 8 + sub;   // nodes nb, nb+4

    float xa[2][8];
    bool act[2];
    #pragma unroll
    for (int j = 0; j < 2; j++) {
        const int n = nb + 4 * j;
        act[j] = (n < NN);
        if (act[j]) {
            const float4* xp = (const float4*)(x + (size_t)n * FF);
            float4 v0 = xp[l], v1 = xp[l + 8];
            xa[j][0]=v0.x; xa[j][1]=v0.y; xa[j][2]=v0.z; xa[j][3]=v0.w;
            xa[j][4]=v1.x; xa[j][5]=v1.y; xa[j][6]=v1.z; xa[j][7]=v1.w;
            float4* hp = (float4*)(g_h + (size_t)n * FF);
            hp[l] = v0; hp[l + 8] = v1;
        } else {
            #pragma unroll
            for (int t = 0; t < 8; t++) xa[j][t] = 0.f;
        }
    }

    const ulonglong2* sW2 = (const ulonglong2*)sW;   // same 16B indexing as float4

    #pragma unroll 1
    for (int m = 0; m < 2; m++) {
        const float* Wsrc = (m == 0) ? Wf : Ws;
        const float* bias = (m == 0) ? bf : bs;
        __syncthreads();
        for (int i = tid; i < 8192; i += 256) sW[i] = Wsrc[i];
        __syncthreads();

        // accA/accB: 4 packed pairs each = 8 floats (chunks l and l+8)
        u64 accA[2][4], accB[2][4];
        #pragma unroll
        for (int j = 0; j < 2; j++) {
            float b0 = bias[4*l],   b1 = bias[4*l+1], b2 = bias[4*l+2], b3 = bias[4*l+3];
            float c0 = bias[32+4*l], c1 = bias[32+4*l+1], c2 = bias[32+4*l+2], c3 = bias[32+4*l+3];
            asm("mov.b64 %0, {%1, %2};" : "=l"(accA[j][0]) : "r"(__float_as_uint(b0)), "r"(__float_as_uint(b1)));
            asm("mov.b64 %0, {%1, %2};" : "=l"(accA[j][1]) : "r"(__float_as_uint(b2)), "r"(__float_as_uint(b3)));
            asm("mov.b64 %0, {%1, %2};" : "=l"(accA[j][2]) : "r"(__float_as_uint(c0)), "r"(__float_as_uint(c1)));
            asm("mov.b64 %0, {%1, %2};" : "=l"(accA[j][3]) : "r"(__float_as_uint(c2)), "r"(__float_as_uint(c3)));
            accB[j][0] = accB[j][1] = accB[j][2] = accB[j][3] = 0ull;
        }

        #pragma unroll
        for (int k = 0; k < 64; k++) {
            const int src = (lane & 24) | ((k >> 2) & 7);
            ulonglong2 wa0 = sW2[k * 16 + l];
            ulonglong2 wa1 = sW2[k * 16 + 8 + l];
            ulonglong2 wb0 = sW2[(64 + k) * 16 + l];
            ulonglong2 wb1 = sW2[(64 + k) * 16 + 8 + l];
            #pragma unroll
            for (int j = 0; j < 2; j++) {
                float xv = __shfl_sync(0xffffffffu, (k < 32) ? xa[j][k & 3] : xa[j][4 + (k & 3)], src);
                u64 xv2; PACK2(xv2, xv);
                FMA2(accA[j][0], xv2, wa0.x, accA[j][0]);
                FMA2(accA[j][1], xv2, wa0.y, accA[j][1]);
                FMA2(accA[j][2], xv2, wa1.x, accA[j][2]);
                FMA2(accA[j][3], xv2, wa1.y, accA[j][3]);
                FMA2(accB[j][0], xv2, wb0.x, accB[j][0]);
                FMA2(accB[j][1], xv2, wb0.y, accB[j][1]);
                FMA2(accB[j][2], xv2, wb1.x, accB[j][2]);
                FMA2(accB[j][3], xv2, wb1.y, accB[j][3]);
            }
        }

        #pragma unroll
        for (int j = 0; j < 2; j++) {
            if (!act[j]) continue;
            const int n = nb + 4 * j;
            ulonglong2* dA = (ulonglong2*)((m == 0 ? g_Af : g_As) + (size_t)n * FF);
            ulonglong2* dB = (ulonglong2*)((m == 0 ? g_Bf : g_Bs) + (size_t)n * FF);
            dA[l]     = make_ulonglong2(accA[j][0], accA[j][1]);
            dA[l + 8] = make_ulonglong2(accA[j][2], accA[j][3]);
            dB[l]     = make_ulonglong2(accB[j][0], accB[j][1]);
            dB[l + 8] = make_ulonglong2(accB[j][2], accB[j][3]);
        }
    }
}

// ---------------- edge kernel ----------------
__device__ __forceinline__ float msgval(float f, float s) {
    float sig = __fdividef(1.f, 1.f + __expf(-f));
    float sp  = fmaxf(s, 0.f) + __logf(1.f + __expf(-fabsf(s)));
    return sig * sp;
}

// 8 lanes per edge, 2 edges per thread; packed f32x2 FMAs; 2 blocks/SM.
// Warp = 8 edges, block = 8 warps = 64 edges. EE % 64 == 0.
__global__ __launch_bounds__(256, 2) void k_edge(
    const int* __restrict__ i32, const long long* __restrict__ i64,
    const float* __restrict__ attr,
    const float* __restrict__ Wf, const float* __restrict__ Ws)
{
    __shared__ float sF[2048], sS[2048];
    const int tid = threadIdx.x;
    for (int i = tid; i < 2048; i += 256) { sF[i] = Wf[8192 + i]; sS[i] = Ws[8192 + i]; }
    __syncthreads();

    const int lane = tid & 31;
    const int l    = lane & 7;
    const int sub  = lane >> 3;
    const int warp = tid >> 5;
    const int use64 = g_use64;
    const ulonglong2* sF2 = (const ulonglong2*)sF;
    const ulonglong2* sS2 = (const ulonglong2*)sS;

    const int ebase = blockIdx.x * 64 + warp * 8 + sub;  // edges ebase, ebase+4

    int dIdx[2];
    float av[2][4];
    u64 accf[2][4], accs[2][4];     // 4 packed pairs each = 8 floats

    #pragma unroll
    for (int j = 0; j < 2; j++) {
        const int e = ebase + 4 * j;
        long long s, d;
        if (use64) { s = i64[e]; d = i64[EE + e]; }
        else       { s = i32[e]; d = i32[EE + e]; }
        dIdx[j] = (int)d;

        float4 a = ((const float4*)attr)[(size_t)e * 8 + l];
        av[j][0] = a.x; av[j][1] = a.y; av[j][2] = a.z; av[j][3] = a.w;

        const ulonglong2* pAf = (const ulonglong2*)(g_Af + (size_t)d * FF);
        const ulonglong2* pBf = (const ulonglong2*)(g_Bf + (size_t)s * FF);
        const ulonglong2* pAs = (const ulonglong2*)(g_As + (size_t)d * FF);
        const ulonglong2* pBs = (const ulonglong2*)(g_Bs + (size_t)s * FF);
        ulonglong2 f0 = pAf[l], f1 = pAf[l + 8];
        ulonglong2 g0 = pBf[l], g1 = pBf[l + 8];
        ulonglong2 s0 = pAs[l], s1 = pAs[l + 8];
        ulonglong2 t0 = pBs[l], t1 = pBs[l + 8];
        ADD2(accf[j][0], f0.x, g0.x); ADD2(accf[j][1], f0.y, g0.y);
        ADD2(accf[j][2], f1.x, g1.x); ADD2(accf[j][3], f1.y, g1.y);
        ADD2(accs[j][0], s0.x, t0.x); ADD2(accs[j][1], s0.y, t0.y);
        ADD2(accs[j][2], s1.x, t1.x); ADD2(accs[j][3], s1.y, t1.y);
    }

    #pragma unroll
    for (int k = 0; k < 32; k++) {
        const int src = (lane & 24) | (k >> 2);
        ulonglong2 wf0 = sF2[k * 16 + l];
        ulonglong2 wf1 = sF2[k * 16 + 8 + l];
        ulonglong2 ws0 = sS2[k * 16 + l];
        ulonglong2 ws1 = sS2[k * 16 + 8 + l];
        #pragma unroll
        for (int j = 0; j < 2; j++) {
            float ak = __shfl_sync(0xffffffffu, av[j][k & 3], src);
            u64 ak2; PACK2(ak2, ak);
            FMA2(accf[j][0], ak2, wf0.x, accf[j][0]);
            FMA2(accf[j][1], ak2, wf0.y, accf[j][1]);
            FMA2(accf[j][2], ak2, wf1.x, accf[j][2]);
            FMA2(accf[j][3], ak2, wf1.y, accf[j][3]);
            FMA2(accs[j][0], ak2, ws0.x, accs[j][0]);
            FMA2(accs[j][1], ak2, ws0.y, accs[j][1]);
            FMA2(accs[j][2], ak2, ws1.x, accs[j][2]);
            FMA2(accs[j][3], ak2, ws1.y, accs[j][3]);
        }
    }

    #pragma unroll
    for (int j = 0; j < 2; j++) {
        float ff[8], ss2[8];
        #pragma unroll
        for (int p = 0; p < 4; p++) {
            unsigned int lo, hi;
            UNPACK2(lo, hi, accf[j][p]); ff[2*p] = __uint_as_float(lo); ff[2*p+1] = __uint_as_float(hi);
            UNPACK2(lo, hi, accs[j][p]); ss2[2*p] = __uint_as_float(lo); ss2[2*p+1] = __uint_as_float(hi);
        }
        float4 m0 = make_float4(msgval(ff[0], ss2[0]), msgval(ff[1], ss2[1]),
                                msgval(ff[2], ss2[2]), msgval(ff[3], ss2[3]));
        float4 m1 = make_float4(msgval(ff[4], ss2[4]), msgval(ff[5], ss2[5]),
                                msgval(ff[6], ss2[6]), msgval(ff[7], ss2[7]));
        float4* ph = (float4*)(g_h + (size_t)dIdx[j] * FF);
        atomicAdd(ph + l,     m0);
        atomicAdd(ph + l + 8, m1);
    }
}

// ---------------- graph-norm ----------------
__global__ void k_zero() {
    int i = blockIdx.x * 256 + threadIdx.x;
    if (i < GG * FF) { g_gsum[i] = 0.f; g_gss[i] = 0.f; }
}

__device__ __forceinline__ long long bget(const int* b32, const long long* b64, int u, int i) {
    return u ? b64[i] : (long long)b32[i];
}

__global__ __launch_bounds__(256) void k_stats(const int* __restrict__ b32,
                                               const long long* __restrict__ b64) {
    const int g = blockIdx.x >> 3;
    const int sp = blockIdx.x & 7;
    const int u = g_use64;

    int lo = 0, hi = NN;
    while (lo < hi) { int mid = (lo + hi) >> 1; if (bget(b32, b64, u, mid) < (long long)g) lo = mid + 1; else hi = mid; }
    const int s0 = lo;
    hi = NN;
    while (lo < hi) { int mid = (lo + hi) >> 1; if (bget(b32, b64, u, mid) < (long long)(g + 1)) lo = mid + 1; else hi = mid; }
    const int s1 = lo;

    const int len = s1 - s0;
    const int chunk = (len + 7) >> 3;
    const int a = s0 + sp * chunk;
    const int b = min(a + chunk, s1);

    const int f = threadIdx.x & 63;
    const int j = threadIdx.x >> 6;
    float sum = 0.f, ss = 0.f;
    for (int n = a + j; n < b; n += 4) {
        float v = g_h[(size_t)n * FF + f];
        sum += v; ss += v * v;
    }
    __shared__ float r1[256], r2[256];
    r1[threadIdx.x] = sum; r2[threadIdx.x] = ss;
    __syncthreads();
    if (j == 0) {
        float t1 = r1[f] + r1[64 + f] + r1[128 + f] + r1[192 + f];
        float t2 = r2[f] + r2[64 + f] + r2[128 + f] + r2[192 + f];
        atomicAdd(&g_gsum[g * 64 + f], t1);
        atomicAdd(&g_gss [g * 64 + f], t2);
    }
    if (sp == 0 && threadIdx.x == 0) g_cnt[g] = (float)len;
}

__global__ void k_prep(const float* __restrict__ gw, const float* __restrict__ gb,
                       const float* __restrict__ gm) {
    int i = blockIdx.x * 256 + threadIdx.x;
    if (i >= GG * FF) return;
    int f = i & 63, g = i >> 6;
    float c    = fmaxf(g_cnt[g], 1.f);
    float inv  = __fdividef(1.f, c);
    float mean = g_gsum[i] * inv;
    float ex2  = g_gss[i] * inv;
    float sub  = gm[f] * mean;
    float var  = ex2 - 2.f * sub * mean + sub * sub;
    float rstd = rsqrtf(var + 1e-5f);
    float al   = gw[f] * rstd;
    g_alpha[i] = al;
    g_beta[i]  = gb[f] - al * sub;
}

__global__ void k_apply(float* __restrict__ out, const int* __restrict__ b32,
                        const long long* __restrict__ b64, int to_internal) {
    int i = blockIdx.x * 256 + threadIdx.x;
    if (i >= NN * FF) return;
    int n = i >> 6, f = i & 63;
    int g = g_use64 ? (int)b64[n] : b32[n];
    float y = g_alpha[g * 64 + f] * g_h[i] + g_beta[g * 64 + f];
    y = (y >= 0.f) ? y : 0.01f * y;
    if (to_internal) g_x2[i] = y; else out[i] = y;
}

// ---------------- launch ----------------
extern "C" void kernel_launch(void* const* d_in, const int* in_sizes, int n_in,
                              void* d_out, int out_size) {
    const float* x    = (const float*)d_in[0];
    const void*  idx  = d_in[1];
    const float* attr = (const float*)d_in[2];
    const void*  bat  = d_in[3];
    const float* Wf1 = (const float*)d_in[4];  const float* bf1 = (const float*)d_in[5];
    const float* Ws1 = (const float*)d_in[6];  const float* bs1 = (const float*)d_in[7];
    const float* gw1 = (const float*)d_in[8];  const float* gb1 = (const float*)d_in[9];
    const float* gm1 = (const float*)d_in[10];
    const float* Wf2 = (const float*)d_in[11]; const float* bf2 = (const float*)d_in[12];
    const float* Ws2 = (const float*)d_in[13]; const float* bs2 = (const float*)d_in[14];
    const float* gw2 = (const float*)d_in[15]; const float* gb2 = (const float*)d_in[16];
    const float* gm2 = (const float*)d_in[17];
    float* out = (float*)d_out;

    const int*       i32 = (const int*)idx;
    const long long* i64 = (const long long*)idx;
    const int*       b32 = (const int*)bat;
    const long long* b64 = (const long long*)bat;

    float* x2ptr = nullptr;
    cudaGetSymbolAddress((void**)&x2ptr, g_x2);

    const int NB_NODE = (NN + 63) / 64;      // 64 nodes / block
    const int NB_EDGE = EE / 64;             // 18750
    const int NB_ELEM = (NN * FF) / 256;

    k_detect<<<1, 256>>>((const int2*)idx);

    // layer 1  (zero before edge so ncu lands on k_edge)
    k_node <<<NB_NODE, 256>>>(x, Wf1, bf1, Ws1, bs1);
    k_zero <<<16, 256>>>();
    k_edge <<<NB_EDGE, 256>>>(i32, i64, attr, Wf1, Ws1);
    k_stats<<<GG * 8, 256>>>(b32, b64);
    k_prep <<<16, 256>>>(gw1, gb1, gm1);
    k_apply<<<NB_ELEM, 256>>>(out, b32, b64, 1);

    // layer 2
    k_node <<<NB_NODE, 256>>>(x2ptr, Wf2, bf2, Ws2, bs2);
    k_zero <<<16, 256>>>();
    k_edge <<<NB_EDGE, 256>>>(i32, i64, attr, Wf2, Ws2);
    k_stats<<<GG * 8, 256>>>(b32, b64);
    k_prep <<<16, 256>>>(gw2, gb2, gm2);
    k_apply<<<NB_ELEM, 256>>>(out, b32, b64, 0);
}

// round 8
// speedup vs baseline: 1.3255x; 1.2667x over previous
#include <cuda_runtime.h>
#include <math.h>

#define NN 100000
#define EE 1200000
#define FF 64
#define DD 32
#define GG 64

typedef unsigned long long u64;

// packed f32x2 helpers (sm_100+; ptxas never auto-generates these)
#define FMA2(d, a, b, c) asm("fma.rn.f32x2 %0, %1, %2, %3;" : "=l"(d) : "l"(a), "l"(b), "l"(c))
#define ADD2(d, a, b)    asm("add.rn.f32x2 %0, %1, %2;"     : "=l"(d) : "l"(a), "l"(b))
#define PACK2(d, s)      asm("mov.b64 %0, {%1, %1};"        : "=l"(d) : "r"(__float_as_uint(s)))
#define UNPACK2(lo, hi, s) asm("mov.b64 {%0, %1}, %2;" : "=r"(lo), "=r"(hi) : "l"(s))

// ---------------- scratch ----------------
__device__ float g_Af[NN * FF];
__device__ float g_Bf[NN * FF];
__device__ float g_As[NN * FF];
__device__ float g_Bs[NN * FF];
__device__ float g_h [NN * FF];   // conv accumulator (init = x, residual folded in)
__device__ float g_x2[NN * FF];
__device__ float g_gsum [GG * FF];
__device__ float g_gss  [GG * FF];
__device__ float g_alpha[GG * FF];
__device__ float g_beta [GG * FF];
__device__ float g_cnt[GG];
__device__ int   g_use64;

// ---------------- int32/int64 runtime detection ----------------
__global__ void k_detect(const int2* __restrict__ idx) {
    __shared__ int any;
    if (threadIdx.x == 0) any = 0;
    __syncthreads();
    int2 v = idx[threadIdx.x];
    if (v.y != 0) any = 1;
    __syncthreads();
    if (threadIdx.x == 0) g_use64 = (any == 0) ? 1 : 0;
}

// ---------------- node linear: Af,Bf,As,Bs + h = x ----------------
// 8 lanes per node, 2 nodes per thread; packed f32x2 FMAs.
__global__ __launch_bounds__(256, 2) void k_node(
    const float* __restrict__ x,
    const float* __restrict__ Wf, const float* __restrict__ bf,
    const float* __restrict__ Ws, const float* __restrict__ bs)
{
    __shared__ float sW[128 * 64];            // full W (32 KB)
    const int tid  = threadIdx.x;
    const int lane = tid & 31;
    const int l    = lane & 7;
    const int sub  = lane >> 3;
    const int warp = tid >> 5;
    const int nb   = (blockIdx.x * 8 + warp) * 8 + sub;   // nodes nb, nb+4

    float xa[2][8];
    bool act[2];
    #pragma unroll
    for (int j = 0; j < 2; j++) {
        const int n = nb + 4 * j;
        act[j] = (n < NN);
        if (act[j]) {
            const float4* xp = (const float4*)(x + (size_t)n * FF);
            float4 v0 = xp[l], v1 = xp[l + 8];
            xa[j][0]=v0.x; xa[j][1]=v0.y; xa[j][2]=v0.z; xa[j][3]=v0.w;
            xa[j][4]=v1.x; xa[j][5]=v1.y; xa[j][6]=v1.z; xa[j][7]=v1.w;
            float4* hp = (float4*)(g_h + (size_t)n * FF);
            hp[l] = v0; hp[l + 8] = v1;
        } else {
            #pragma unroll
            for (int t = 0; t < 8; t++) xa[j][t] = 0.f;
        }
    }

    const ulonglong2* sW2 = (const ulonglong2*)sW;

    #pragma unroll 1
    for (int m = 0; m < 2; m++) {
        const float* Wsrc = (m == 0) ? Wf : Ws;
        const float* bias = (m == 0) ? bf : bs;
        __syncthreads();
        for (int i = tid; i < 8192; i += 256) sW[i] = Wsrc[i];
        __syncthreads();

        u64 accA[2][4], accB[2][4];
        #pragma unroll
        for (int j = 0; j < 2; j++) {
            float b0 = bias[4*l],   b1 = bias[4*l+1], b2 = bias[4*l+2], b3 = bias[4*l+3];
            float c0 = bias[32+4*l], c1 = bias[32+4*l+1], c2 = bias[32+4*l+2], c3 = bias[32+4*l+3];
            asm("mov.b64 %0, {%1, %2};" : "=l"(accA[j][0]) : "r"(__float_as_uint(b0)), "r"(__float_as_uint(b1)));
            asm("mov.b64 %0, {%1, %2};" : "=l"(accA[j][1]) : "r"(__float_as_uint(b2)), "r"(__float_as_uint(b3)));
            asm("mov.b64 %0, {%1, %2};" : "=l"(accA[j][2]) : "r"(__float_as_uint(c0)), "r"(__float_as_uint(c1)));
            asm("mov.b64 %0, {%1, %2};" : "=l"(accA[j][3]) : "r"(__float_as_uint(c2)), "r"(__float_as_uint(c3)));
            accB[j][0] = accB[j][1] = accB[j][2] = accB[j][3] = 0ull;
        }

        #pragma unroll
        for (int k = 0; k < 64; k++) {
            const int src = (lane & 24) | ((k >> 2) & 7);
            ulonglong2 wa0 = sW2[k * 16 + l];
            ulonglong2 wa1 = sW2[k * 16 + 8 + l];
            ulonglong2 wb0 = sW2[(64 + k) * 16 + l];
            ulonglong2 wb1 = sW2[(64 + k) * 16 + 8 + l];
            #pragma unroll
            for (int j = 0; j < 2; j++) {
                float xv = __shfl_sync(0xffffffffu, (k < 32) ? xa[j][k & 3] : xa[j][4 + (k & 3)], src);
                u64 xv2; PACK2(xv2, xv);
                FMA2(accA[j][0], xv2, wa0.x, accA[j][0]);
                FMA2(accA[j][1], xv2, wa0.y, accA[j][1]);
                FMA2(accA[j][2], xv2, wa1.x, accA[j][2]);
                FMA2(accA[j][3], xv2, wa1.y, accA[j][3]);
                FMA2(accB[j][0], xv2, wb0.x, accB[j][0]);
                FMA2(accB[j][1], xv2, wb0.y, accB[j][1]);
                FMA2(accB[j][2], xv2, wb1.x, accB[j][2]);
                FMA2(accB[j][3], xv2, wb1.y, accB[j][3]);
            }
        }

        #pragma unroll
        for (int j = 0; j < 2; j++) {
            if (!act[j]) continue;
            const int n = nb + 4 * j;
            ulonglong2* dA = (ulonglong2*)((m == 0 ? g_Af : g_As) + (size_t)n * FF);
            ulonglong2* dB = (ulonglong2*)((m == 0 ? g_Bf : g_Bs) + (size_t)n * FF);
            dA[l]     = make_ulonglong2(accA[j][0], accA[j][1]);
            dA[l + 8] = make_ulonglong2(accA[j][2], accA[j][3]);
            dB[l]     = make_ulonglong2(accB[j][0], accB[j][1]);
            dB[l + 8] = make_ulonglong2(accB[j][2], accB[j][3]);
        }
    }
}

// ---------------- edge kernel ----------------
__device__ __forceinline__ float msgval(float f, float s) {
    float sig = __fdividef(1.f, 1.f + __expf(-f));
    float sp  = fmaxf(s, 0.f) + __logf(1.f + __expf(-fabsf(s)));
    return sig * sp;
}

// 8 lanes per edge, 4 edges per thread (LDS amortized 4x), packed f32x2 FMAs.
// Warp = 16 edges, block = 8 warps = 128 edges. EE % 128 == 0.
__global__ __launch_bounds__(256, 2) void k_edge(
    const int* __restrict__ i32, const long long* __restrict__ i64,
    const float* __restrict__ attr,
    const float* __restrict__ Wf, const float* __restrict__ Ws)
{
    __shared__ float sF[2048], sS[2048];
    const int tid = threadIdx.x;
    for (int i = tid; i < 2048; i += 256) { sF[i] = Wf[8192 + i]; sS[i] = Ws[8192 + i]; }
    __syncthreads();

    const int lane = tid & 31;
    const int l    = lane & 7;
    const int sub  = lane >> 3;
    const int warp = tid >> 5;
    const int use64 = g_use64;
    const ulonglong2* sF2 = (const ulonglong2*)sF;
    const ulonglong2* sS2 = (const ulonglong2*)sS;

    const int ebase = blockIdx.x * 128 + warp * 16 + sub;  // edges ebase + 4j

    int dIdx[4];
    float av[4][4];
    u64 accf[4][4], accs[4][4];     // 4 packed pairs each = 8 floats per edge

    #pragma unroll
    for (int j = 0; j < 4; j++) {
        const int e = ebase + 4 * j;
        long long s, d;
        if (use64) { s = i64[e]; d = i64[EE + e]; }
        else       { s = i32[e]; d = i32[EE + e]; }
        dIdx[j] = (int)d;

        float4 a = ((const float4*)attr)[(size_t)e * 8 + l];
        av[j][0] = a.x; av[j][1] = a.y; av[j][2] = a.z; av[j][3] = a.w;

        const ulonglong2* pAf = (const ulonglong2*)(g_Af + (size_t)d * FF);
        const ulonglong2* pBf = (const ulonglong2*)(g_Bf + (size_t)s * FF);
        const ulonglong2* pAs = (const ulonglong2*)(g_As + (size_t)d * FF);
        const ulonglong2* pBs = (const ulonglong2*)(g_Bs + (size_t)s * FF);
        ulonglong2 f0 = pAf[l], f1 = pAf[l + 8];
        ulonglong2 g0 = pBf[l], g1 = pBf[l + 8];
        ulonglong2 s0 = pAs[l], s1 = pAs[l + 8];
        ulonglong2 t0 = pBs[l], t1 = pBs[l + 8];
        ADD2(accf[j][0], f0.x, g0.x); ADD2(accf[j][1], f0.y, g0.y);
        ADD2(accf[j][2], f1.x, g1.x); ADD2(accf[j][3], f1.y, g1.y);
        ADD2(accs[j][0], s0.x, t0.x); ADD2(accs[j][1], s0.y, t0.y);
        ADD2(accs[j][2], s1.x, t1.x); ADD2(accs[j][3], s1.y, t1.y);
    }

    #pragma unroll
    for (int k = 0; k < 32; k++) {
        const int src = (lane & 24) | (k >> 2);
        ulonglong2 wf0 = sF2[k * 16 + l];
        ulonglong2 wf1 = sF2[k * 16 + 8 + l];
        ulonglong2 ws0 = sS2[k * 16 + l];
        ulonglong2 ws1 = sS2[k * 16 + 8 + l];
        #pragma unroll
        for (int j = 0; j < 4; j++) {
            float ak = __shfl_sync(0xffffffffu, av[j][k & 3], src);
            u64 ak2; PACK2(ak2, ak);
            FMA2(accf[j][0], ak2, wf0.x, accf[j][0]);
            FMA2(accf[j][1], ak2, wf0.y, accf[j][1]);
            FMA2(accf[j][2], ak2, wf1.x, accf[j][2]);
            FMA2(accf[j][3], ak2, wf1.y, accf[j][3]);
            FMA2(accs[j][0], ak2, ws0.x, accs[j][0]);
            FMA2(accs[j][1], ak2, ws0.y, accs[j][1]);
            FMA2(accs[j][2], ak2, ws1.x, accs[j][2]);
            FMA2(accs[j][3], ak2, ws1.y, accs[j][3]);
        }
    }

    #pragma unroll
    for (int j = 0; j < 4; j++) {
        float ff[8], ss2[8];
        #pragma unroll
        for (int p = 0; p < 4; p++) {
            unsigned int lo, hi;
            UNPACK2(lo, hi, accf[j][p]); ff[2*p] = __uint_as_float(lo); ff[2*p+1] = __uint_as_float(hi);
            UNPACK2(lo, hi, accs[j][p]); ss2[2*p] = __uint_as_float(lo); ss2[2*p+1] = __uint_as_float(hi);
        }
        float4 m0 = make_float4(msgval(ff[0], ss2[0]), msgval(ff[1], ss2[1]),
                                msgval(ff[2], ss2[2]), msgval(ff[3], ss2[3]));
        float4 m1 = make_float4(msgval(ff[4], ss2[4]), msgval(ff[5], ss2[5]),
                                msgval(ff[6], ss2[6]), msgval(ff[7], ss2[7]));
        float4* ph = (float4*)(g_h + (size_t)dIdx[j] * FF);
        atomicAdd(ph + l,     m0);
        atomicAdd(ph + l + 8, m1);
    }
}

// ---------------- graph-norm ----------------
__global__ void k_zero() {
    int i = blockIdx.x * 256 + threadIdx.x;
    if (i < GG * FF) { g_gsum[i] = 0.f; g_gss[i] = 0.f; }
}

__device__ __forceinline__ long long bget(const int* b32, const long long* b64, int u, int i) {
    return u ? b64[i] : (long long)b32[i];
}

__global__ __launch_bounds__(256) void k_stats(const int* __restrict__ b32,
                                               const long long* __restrict__ b64) {
    const int g = blockIdx.x >> 3;
    const int sp = blockIdx.x & 7;
    const int u = g_use64;

    int lo = 0, hi = NN;
    while (lo < hi) { int mid = (lo + hi) >> 1; if (bget(b32, b64, u, mid) < (long long)g) lo = mid + 1; else hi = mid; }
    const int s0 = lo;
    hi = NN;
    while (lo < hi) { int mid = (lo + hi) >> 1; if (bget(b32, b64, u, mid) < (long long)(g + 1)) lo = mid + 1; else hi = mid; }
    const int s1 = lo;

    const int len = s1 - s0;
    const int chunk = (len + 7) >> 3;
    const int a = s0 + sp * chunk;
    const int b = min(a + chunk, s1);

    const int f = threadIdx.x & 63;
    const int j = threadIdx.x >> 6;
    float sum = 0.f, ss = 0.f;
    for (int n = a + j; n < b; n += 4) {
        float v = g_h[(size_t)n * FF + f];
        sum += v; ss += v * v;
    }
    __shared__ float r1[256], r2[256];
    r1[threadIdx.x] = sum; r2[threadIdx.x] = ss;
    __syncthreads();
    if (j == 0) {
        float t1 = r1[f] + r1[64 + f] + r1[128 + f] + r1[192 + f];
        float t2 = r2[f] + r2[64 + f] + r2[128 + f] + r2[192 + f];
        atomicAdd(&g_gsum[g * 64 + f], t1);
        atomicAdd(&g_gss [g * 64 + f], t2);
    }
    if (sp == 0 && threadIdx.x == 0) g_cnt[g] = (float)len;
}

__global__ void k_prep(const float* __restrict__ gw, const float* __restrict__ gb,
                       const float* __restrict__ gm) {
    int i = blockIdx.x * 256 + threadIdx.x;
    if (i >= GG * FF) return;
    int f = i & 63, g = i >> 6;
    float c    = fmaxf(g_cnt[g], 1.f);
    float inv  = __fdividef(1.f, c);
    float mean = g_gsum[i] * inv;
    float ex2  = g_gss[i] * inv;
    float sub  = gm[f] * mean;
    float var  = ex2 - 2.f * sub * mean + sub * sub;
    float rstd = rsqrtf(var + 1e-5f);
    float al   = gw[f] * rstd;
    g_alpha[i] = al;
    g_beta[i]  = gb[f] - al * sub;
}

__global__ void k_apply(float* __restrict__ out, const int* __restrict__ b32,
                        const long long* __restrict__ b64, int to_internal) {
    int i = blockIdx.x * 256 + threadIdx.x;
    if (i >= NN * FF) return;
    int n = i >> 6, f = i & 63;
    int g = g_use64 ? (int)b64[n] : b32[n];
    float y = g_alpha[g * 64 + f] * g_h[i] + g_beta[g * 64 + f];
    y = (y >= 0.f) ? y : 0.01f * y;
    if (to_internal) g_x2[i] = y; else out[i] = y;
}

// ---------------- launch ----------------
extern "C" void kernel_launch(void* const* d_in, const int* in_sizes, int n_in,
                              void* d_out, int out_size) {
    const float* x    = (const float*)d_in[0];
    const void*  idx  = d_in[1];
    const float* attr = (const float*)d_in[2];
    const void*  bat  = d_in[3];
    const float* Wf1 = (const float*)d_in[4];  const float* bf1 = (const float*)d_in[5];
    const float* Ws1 = (const float*)d_in[6];  const float* bs1 = (const float*)d_in[7];
    const float* gw1 = (const float*)d_in[8];  const float* gb1 = (const float*)d_in[9];
    const float* gm1 = (const float*)d_in[10];
    const float* Wf2 = (const float*)d_in[11]; const float* bf2 = (const float*)d_in[12];
    const float* Ws2 = (const float*)d_in[13]; const float* bs2 = (const float*)d_in[14];
    const float* gw2 = (const float*)d_in[15]; const float* gb2 = (const float*)d_in[16];
    const float* gm2 = (const float*)d_in[17];
    float* out = (float*)d_out;

    const int*       i32 = (const int*)idx;
    const long long* i64 = (const long long*)idx;
    const int*       b32 = (const int*)bat;
    const long long* b64 = (const long long*)bat;

    float* x2ptr = nullptr;
    cudaGetSymbolAddress((void**)&x2ptr, g_x2);

    const int NB_NODE = (NN + 63) / 64;      // 64 nodes / block
    const int NB_EDGE = EE / 128;            // 9375
    const int NB_ELEM = (NN * FF) / 256;

    k_detect<<<1, 256>>>((const int2*)idx);

    // layer 1  (zero before edge so ncu lands on k_edge)
    k_node <<<NB_NODE, 256>>>(x, Wf1, bf1, Ws1, bs1);
    k_zero <<<16, 256>>>();
    k_edge <<<NB_EDGE, 256>>>(i32, i64, attr, Wf1, Ws1);
    k_stats<<<GG * 8, 256>>>(b32, b64);
    k_prep <<<16, 256>>>(gw1, gb1, gm1);
    k_apply<<<NB_ELEM, 256>>>(out, b32, b64, 1);

    // layer 2
    k_node <<<NB_NODE, 256>>>(x2ptr, Wf2, bf2, Ws2, bs2);
    k_zero <<<16, 256>>>();
    k_edge <<<NB_EDGE, 256>>>(i32, i64, attr, Wf2, Ws2);
    k_stats<<<GG * 8, 256>>>(b32, b64);
    k_prep <<<16, 256>>>(gw2, gb2, gm2);
    k_apply<<<NB_ELEM, 256>>>(out, b32, b64, 0);
}

// round 9
// speedup vs baseline: 1.3281x; 1.0019x over previous
#include <cuda_runtime.h>
#include <math.h>

#define NN 100000
#define EE 1200000
#define FF 64
#define DD 32
#define GG 64

typedef unsigned long long u64;

// packed f32x2 helpers (sm_100+; ptxas never auto-generates these)
#define FMA2(d, a, b, c) asm("fma.rn.f32x2 %0, %1, %2, %3;" : "=l"(d) : "l"(a), "l"(b), "l"(c))
#define ADD2(d, a, b)    asm("add.rn.f32x2 %0, %1, %2;"     : "=l"(d) : "l"(a), "l"(b))
#define PACK2(d, s)      asm("mov.b64 %0, {%1, %1};"        : "=l"(d) : "r"(__float_as_uint(s)))
#define UNPACK2(lo, hi, s) asm("mov.b64 {%0, %1}, %2;" : "=r"(lo), "=r"(hi) : "l"(s))

// ---------------- scratch ----------------
__device__ float g_Af[NN * FF];
__device__ float g_Bf[NN * FF];
__device__ float g_As[NN * FF];
__device__ float g_Bs[NN * FF];
__device__ float g_h [NN * FF];   // conv accumulator (init = x or normed h, residual folded)
__device__ float g_p1[GG * 8 * FF];   // stats partials (no atomics, no zeroing)
__device__ float g_p2[GG * 8 * FF];
__device__ float g_alpha[GG * FF];
__device__ float g_beta [GG * FF];
__device__ float g_cnt[GG];
__device__ int   g_use64;

// ---------------- int32/int64 runtime detection ----------------
__global__ void k_detect(const int2* __restrict__ idx) {
    __shared__ int any;
    if (threadIdx.x == 0) any = 0;
    __syncthreads();
    int2 v = idx[threadIdx.x];
    if (v.y != 0) any = 1;
    __syncthreads();
    if (threadIdx.x == 0) g_use64 = (any == 0) ? 1 : 0;
}

__device__ __forceinline__ float lrelu(float y) { return (y >= 0.f) ? y : 0.01f * y; }

// ---------------- node linear: Af,Bf,As,Bs + h init ----------------
// 8 lanes per node, 2 nodes per thread, single k-pass, weights via L1 LDG.
// fused=1: input = leaky(alpha*g_h+beta) (GraphNorm of prev layer), rewritten into g_h.
__global__ __launch_bounds__(256, 2) void k_node(
    const float* __restrict__ x,
    const float* __restrict__ Wf, const float* __restrict__ bf,
    const float* __restrict__ Ws, const float* __restrict__ bs,
    int fused, const int* __restrict__ b32, const long long* __restrict__ b64)
{
    const int tid  = threadIdx.x;
    const int lane = tid & 31;
    const int l    = lane & 7;
    const int sub  = lane >> 3;
    const int warp = tid >> 5;
    const int nb   = (blockIdx.x * 8 + warp) * 8 + sub;   // nodes nb, nb+4

    float xa[2][8];
    bool act[2];
    #pragma unroll
    for (int j = 0; j < 2; j++) {
        const int n = nb + 4 * j;
        act[j] = (n < NN);
        if (act[j]) {
            float4* hp = (float4*)(g_h + (size_t)n * FF);
            float4 v0, v1;
            if (!fused) {
                const float4* xp = (const float4*)(x + (size_t)n * FF);
                v0 = xp[l]; v1 = xp[l + 8];
            } else {
                int g = g_use64 ? (int)b64[n] : b32[n];
                float4 h0 = hp[l], h1 = hp[l + 8];
                const float4* al = (const float4*)(g_alpha + g * 64);
                const float4* be = (const float4*)(g_beta  + g * 64);
                float4 a0 = al[l], a1 = al[l + 8], c0 = be[l], c1 = be[l + 8];
                v0.x = lrelu(fmaf(a0.x, h0.x, c0.x)); v0.y = lrelu(fmaf(a0.y, h0.y, c0.y));
                v0.z = lrelu(fmaf(a0.z, h0.z, c0.z)); v0.w = lrelu(fmaf(a0.w, h0.w, c0.w));
                v1.x = lrelu(fmaf(a1.x, h1.x, c1.x)); v1.y = lrelu(fmaf(a1.y, h1.y, c1.y));
                v1.z = lrelu(fmaf(a1.z, h1.z, c1.z)); v1.w = lrelu(fmaf(a1.w, h1.w, c1.w));
            }
            hp[l] = v0; hp[l + 8] = v1;       // residual init
            xa[j][0]=v0.x; xa[j][1]=v0.y; xa[j][2]=v0.z; xa[j][3]=v0.w;
            xa[j][4]=v1.x; xa[j][5]=v1.y; xa[j][6]=v1.z; xa[j][7]=v1.w;
        } else {
            #pragma unroll
            for (int t = 0; t < 8; t++) xa[j][t] = 0.f;
        }
    }

    u64 aAf[2][4], aBf[2][4], aAs[2][4], aBs[2][4];
    #pragma unroll
    for (int j = 0; j < 2; j++) {
        #pragma unroll
        for (int p = 0; p < 2; p++) {
            const float* bofs = (p == 0) ? (bf + 4 * l) : (bf + 32 + 4 * l);
            const float* sofs = (p == 0) ? (bs + 4 * l) : (bs + 32 + 4 * l);
            asm("mov.b64 %0, {%1, %2};" : "=l"(aAf[j][2*p])   : "r"(__float_as_uint(bofs[0])), "r"(__float_as_uint(bofs[1])));
            asm("mov.b64 %0, {%1, %2};" : "=l"(aAf[j][2*p+1]) : "r"(__float_as_uint(bofs[2])), "r"(__float_as_uint(bofs[3])));
            asm("mov.b64 %0, {%1, %2};" : "=l"(aAs[j][2*p])   : "r"(__float_as_uint(sofs[0])), "r"(__float_as_uint(sofs[1])));
            asm("mov.b64 %0, {%1, %2};" : "=l"(aAs[j][2*p+1]) : "r"(__float_as_uint(sofs[2])), "r"(__float_as_uint(sofs[3])));
        }
        aBf[j][0]=aBf[j][1]=aBf[j][2]=aBf[j][3]=0ull;
        aBs[j][0]=aBs[j][1]=aBs[j][2]=aBs[j][3]=0ull;
    }

    const ulonglong2* WfA = (const ulonglong2*)Wf;            // rows 0..63
    const ulonglong2* WfB = (const ulonglong2*)(Wf + 4096);   // rows 64..127
    const ulonglong2* WsA = (const ulonglong2*)Ws;
    const ulonglong2* WsB = (const ulonglong2*)(Ws + 4096);

    #pragma unroll 8
    for (int k = 0; k < 64; k++) {
        const int src = (lane & 24) | ((k >> 2) & 7);
        ulonglong2 wfa0 = WfA[k * 16 + l],     wfa1 = WfA[k * 16 + 8 + l];
        ulonglong2 wfb0 = WfB[k * 16 + l],     wfb1 = WfB[k * 16 + 8 + l];
        ulonglong2 wsa0 = WsA[k * 16 + l],     wsa1 = WsA[k * 16 + 8 + l];
        ulonglong2 wsb0 = WsB[k * 16 + l],     wsb1 = WsB[k * 16 + 8 + l];
        #pragma unroll
        for (int j = 0; j < 2; j++) {
            float xv = __shfl_sync(0xffffffffu, (k < 32) ? xa[j][k & 3] : xa[j][4 + (k & 3)], src);
            u64 xv2; PACK2(xv2, xv);
            FMA2(aAf[j][0], xv2, wfa0.x, aAf[j][0]);
            FMA2(aAf[j][1], xv2, wfa0.y, aAf[j][1]);
            FMA2(aAf[j][2], xv2, wfa1.x, aAf[j][2]);
            FMA2(aAf[j][3], xv2, wfa1.y, aAf[j][3]);
            FMA2(aBf[j][0], xv2, wfb0.x, aBf[j][0]);
            FMA2(aBf[j][1], xv2, wfb0.y, aBf[j][1]);
            FMA2(aBf[j][2], xv2, wfb1.x, aBf[j][2]);
            FMA2(aBf[j][3], xv2, wfb1.y, aBf[j][3]);
            FMA2(aAs[j][0], xv2, wsa0.x, aAs[j][0]);
            FMA2(aAs[j][1], xv2, wsa0.y, aAs[j][1]);
            FMA2(aAs[j][2], xv2, wsa1.x, aAs[j][2]);
            FMA2(aAs[j][3], xv2, wsa1.y, aAs[j][3]);
            FMA2(aBs[j][0], xv2, wsb0.x, aBs[j][0]);
            FMA2(aBs[j][1], xv2, wsb0.y, aBs[j][1]);
            FMA2(aBs[j][2], xv2, wsb1.x, aBs[j][2]);
            FMA2(aBs[j][3], xv2, wsb1.y, aBs[j][3]);
        }
    }

    #pragma unroll
    for (int j = 0; j < 2; j++) {
        if (!act[j]) continue;
        const int n = nb + 4 * j;
        ulonglong2* dAf = (ulonglong2*)(g_Af + (size_t)n * FF);
        ulonglong2* dBf = (ulonglong2*)(g_Bf + (size_t)n * FF);
        ulonglong2* dAs = (ulonglong2*)(g_As + (size_t)n * FF);
        ulonglong2* dBs = (ulonglong2*)(g_Bs + (size_t)n * FF);
        dAf[l] = make_ulonglong2(aAf[j][0], aAf[j][1]); dAf[l+8] = make_ulonglong2(aAf[j][2], aAf[j][3]);
        dBf[l] = make_ulonglong2(aBf[j][0], aBf[j][1]); dBf[l+8] = make_ulonglong2(aBf[j][2], aBf[j][3]);
        dAs[l] = make_ulonglong2(aAs[j][0], aAs[j][1]); dAs[l+8] = make_ulonglong2(aAs[j][2], aAs[j][3]);
        dBs[l] = make_ulonglong2(aBs[j][0], aBs[j][1]); dBs[l+8] = make_ulonglong2(aBs[j][2], aBs[j][3]);
    }
}

// ---------------- edge kernel (unchanged from round 8) ----------------
__device__ __forceinline__ float msgval(float f, float s) {
    float sig = __fdividef(1.f, 1.f + __expf(-f));
    float sp  = fmaxf(s, 0.f) + __logf(1.f + __expf(-fabsf(s)));
    return sig * sp;
}

__global__ __launch_bounds__(256, 2) void k_edge(
    const int* __restrict__ i32, const long long* __restrict__ i64,
    const float* __restrict__ attr,
    const float* __restrict__ Wf, const float* __restrict__ Ws)
{
    __shared__ float sF[2048], sS[2048];
    const int tid = threadIdx.x;
    for (int i = tid; i < 2048; i += 256) { sF[i] = Wf[8192 + i]; sS[i] = Ws[8192 + i]; }
    __syncthreads();

    const int lane = tid & 31;
    const int l    = lane & 7;
    const int sub  = lane >> 3;
    const int warp = tid >> 5;
    const int use64 = g_use64;
    const ulonglong2* sF2 = (const ulonglong2*)sF;
    const ulonglong2* sS2 = (const ulonglong2*)sS;

    const int ebase = blockIdx.x * 128 + warp * 16 + sub;

    int dIdx[4];
    float av[4][4];
    u64 accf[4][4], accs[4][4];

    #pragma unroll
    for (int j = 0; j < 4; j++) {
        const int e = ebase + 4 * j;
        long long s, d;
        if (use64) { s = i64[e]; d = i64[EE + e]; }
        else       { s = i32[e]; d = i32[EE + e]; }
        dIdx[j] = (int)d;

        float4 a = ((const float4*)attr)[(size_t)e * 8 + l];
        av[j][0] = a.x; av[j][1] = a.y; av[j][2] = a.z; av[j][3] = a.w;

        const ulonglong2* pAf = (const ulonglong2*)(g_Af + (size_t)d * FF);
        const ulonglong2* pBf = (const ulonglong2*)(g_Bf + (size_t)s * FF);
        const ulonglong2* pAs = (const ulonglong2*)(g_As + (size_t)d * FF);
        const ulonglong2* pBs = (const ulonglong2*)(g_Bs + (size_t)s * FF);
        ulonglong2 f0 = pAf[l], f1 = pAf[l + 8];
        ulonglong2 g0 = pBf[l], g1 = pBf[l + 8];
        ulonglong2 s0 = pAs[l], s1 = pAs[l + 8];
        ulonglong2 t0 = pBs[l], t1 = pBs[l + 8];
        ADD2(accf[j][0], f0.x, g0.x); ADD2(accf[j][1], f0.y, g0.y);
        ADD2(accf[j][2], f1.x, g1.x); ADD2(accf[j][3], f1.y, g1.y);
        ADD2(accs[j][0], s0.x, t0.x); ADD2(accs[j][1], s0.y, t0.y);
        ADD2(accs[j][2], s1.x, t1.x); ADD2(accs[j][3], s1.y, t1.y);
    }

    #pragma unroll
    for (int k = 0; k < 32; k++) {
        const int src = (lane & 24) | (k >> 2);
        ulonglong2 wf0 = sF2[k * 16 + l];
        ulonglong2 wf1 = sF2[k * 16 + 8 + l];
        ulonglong2 ws0 = sS2[k * 16 + l];
        ulonglong2 ws1 = sS2[k * 16 + 8 + l];
        #pragma unroll
        for (int j = 0; j < 4; j++) {
            float ak = __shfl_sync(0xffffffffu, av[j][k & 3], src);
            u64 ak2; PACK2(ak2, ak);
            FMA2(accf[j][0], ak2, wf0.x, accf[j][0]);
            FMA2(accf[j][1], ak2, wf0.y, accf[j][1]);
            FMA2(accf[j][2], ak2, wf1.x, accf[j][2]);
            FMA2(accf[j][3], ak2, wf1.y, accf[j][3]);
            FMA2(accs[j][0], ak2, ws0.x, accs[j][0]);
            FMA2(accs[j][1], ak2, ws0.y, accs[j][1]);
            FMA2(accs[j][2], ak2, ws1.x, accs[j][2]);
            FMA2(accs[j][3], ak2, ws1.y, accs[j][3]);
        }
    }

    #pragma unroll
    for (int j = 0; j < 4; j++) {
        float ff[8], ss2[8];
        #pragma unroll
        for (int p = 0; p < 4; p++) {
            unsigned int lo, hi;
            UNPACK2(lo, hi, accf[j][p]); ff[2*p] = __uint_as_float(lo); ff[2*p+1] = __uint_as_float(hi);
            UNPACK2(lo, hi, accs[j][p]); ss2[2*p] = __uint_as_float(lo); ss2[2*p+1] = __uint_as_float(hi);
        }
        float4 m0 = make_float4(msgval(ff[0], ss2[0]), msgval(ff[1], ss2[1]),
                                msgval(ff[2], ss2[2]), msgval(ff[3], ss2[3]));
        float4 m1 = make_float4(msgval(ff[4], ss2[4]), msgval(ff[5], ss2[5]),
                                msgval(ff[6], ss2[6]), msgval(ff[7], ss2[7]));
        float4* ph = (float4*)(g_h + (size_t)dIdx[j] * FF);
        atomicAdd(ph + l,     m0);
        atomicAdd(ph + l + 8, m1);
    }
}

// ---------------- graph-norm ----------------
__device__ __forceinline__ long long bget(const int* b32, const long long* b64, int u, int i) {
    return u ? b64[i] : (long long)b32[i];
}

__global__ __launch_bounds__(256) void k_stats(const int* __restrict__ b32,
                                               const long long* __restrict__ b64) {
    const int g = blockIdx.x >> 3;
    const int sp = blockIdx.x & 7;
    const int u = g_use64;

    int lo = 0, hi = NN;
    while (lo < hi) { int mid = (lo + hi) >> 1; if (bget(b32, b64, u, mid) < (long long)g) lo = mid + 1; else hi = mid; }
    const int s0 = lo;
    hi = NN;
    while (lo < hi) { int mid = (lo + hi) >> 1; if (bget(b32, b64, u, mid) < (long long)(g + 1)) lo = mid + 1; else hi = mid; }
    const int s1 = lo;

    const int len = s1 - s0;
    const int chunk = (len + 7) >> 3;
    const int a = s0 + sp * chunk;
    const int b = min(a + chunk, s1);

    const int f = threadIdx.x & 63;
    const int j = threadIdx.x >> 6;
    float sum = 0.f, ss = 0.f;
    for (int n = a + j; n < b; n += 4) {
        float v = g_h[(size_t)n * FF + f];
        sum += v; ss += v * v;
    }
    __shared__ float r1[256], r2[256];
    r1[threadIdx.x] = sum; r2[threadIdx.x] = ss;
    __syncthreads();
    if (j == 0) {
        g_p1[(g * 8 + sp) * 64 + f] = r1[f] + r1[64 + f] + r1[128 + f] + r1[192 + f];
        g_p2[(g * 8 + sp) * 64 + f] = r2[f] + r2[64 + f] + r2[128 + f] + r2[192 + f];
    }
    if (sp == 0 && threadIdx.x == 0) g_cnt[g] = (float)len;
}

__global__ void k_prep(const float* __restrict__ gw, const float* __restrict__ gb,
                       const float* __restrict__ gm) {
    int i = blockIdx.x * 256 + threadIdx.x;
    if (i >= GG * FF) return;
    int f = i & 63, g = i >> 6;
    float s1 = 0.f, s2 = 0.f;
    #pragma unroll
    for (int sp = 0; sp < 8; sp++) {
        s1 += g_p1[(g * 8 + sp) * 64 + f];
        s2 += g_p2[(g * 8 + sp) * 64 + f];
    }
    float c    = fmaxf(g_cnt[g], 1.f);
    float inv  = __fdividef(1.f, c);
    float mean = s1 * inv;
    float ex2  = s2 * inv;
    float sub  = gm[f] * mean;
    float var  = ex2 - 2.f * sub * mean + sub * sub;
    float rstd = rsqrtf(var + 1e-5f);
    float al   = gw[f] * rstd;
    g_alpha[i] = al;
    g_beta[i]  = gb[f] - al * sub;
}

__global__ void k_apply(float* __restrict__ out, const int* __restrict__ b32,
                        const long long* __restrict__ b64) {
    int i = blockIdx.x * 256 + threadIdx.x;
    if (i >= NN * FF) return;
    int n = i >> 6, f = i & 63;
    int g = g_use64 ? (int)b64[n] : b32[n];
    float y = g_alpha[g * 64 + f] * g_h[i] + g_beta[g * 64 + f];
    out[i] = lrelu(y);
}

// ---------------- launch ----------------
extern "C" void kernel_launch(void* const* d_in, const int* in_sizes, int n_in,
                              void* d_out, int out_size) {
    const float* x    = (const float*)d_in[0];
    const void*  idx  = d_in[1];
    const float* attr = (const float*)d_in[2];
    const void*  bat  = d_in[3];
    const float* Wf1 = (const float*)d_in[4];  const float* bf1 = (const float*)d_in[5];
    const float* Ws1 = (const float*)d_in[6];  const float* bs1 = (const float*)d_in[7];
    const float* gw1 = (const float*)d_in[8];  const float* gb1 = (const float*)d_in[9];
    const float* gm1 = (const float*)d_in[10];
    const float* Wf2 = (const float*)d_in[11]; const float* bf2 = (const float*)d_in[12];
    const float* Ws2 = (const float*)d_in[13]; const float* bs2 = (const float*)d_in[14];
    const float* gw2 = (const float*)d_in[15]; const float* gb2 = (const float*)d_in[16];
    const float* gm2 = (const float*)d_in[17];
    float* out = (float*)d_out;

    const int*       i32 = (const int*)idx;
    const long long* i64 = (const long long*)idx;
    const int*       b32 = (const int*)bat;
    const long long* b64 = (const long long*)bat;

    const int NB_NODE = (NN + 63) / 64;      // 64 nodes / block
    const int NB_EDGE = EE / 128;            // 9375
    const int NB_ELEM = (NN * FF) / 256;

    k_detect<<<1, 256>>>((const int2*)idx);

    // layer 1
    k_node <<<NB_NODE, 256>>>(x, Wf1, bf1, Ws1, bs1, 0, b32, b64);
    k_edge <<<NB_EDGE, 256>>>(i32, i64, attr, Wf1, Ws1);
    k_stats<<<GG * 8, 256>>>(b32, b64);
    k_prep <<<16, 256>>>(gw1, gb1, gm1);

    // layer 2 (norm1+leaky applied inside k_node on the fly)
    k_node <<<NB_NODE, 256>>>(nullptr, Wf2, bf2, Ws2, bs2, 1, b32, b64);
    k_edge <<<NB_EDGE, 256>>>(i32, i64, attr, Wf2, Ws2);
    k_stats<<<GG * 8, 256>>>(b32, b64);
    k_prep <<<16, 256>>>(gw2, gb2, gm2);
    k_apply<<<NB_ELEM, 256>>>(out, b32, b64);
}